// round 15
// baseline (speedup 1.0000x reference)
#include <cuda_runtime.h>
#include <cuda_bf16.h>
#include <cstdint>

// LSTM_53815940218945 via mma.sync bf16x3 (Ootomo split), round 15:
// TWO independent CTAs per SM (MB=32, 256 thr, launch_bounds(256,2)) so the
// per-step barrier/latency tails of the two CTAs overlap each other's MMA.
// CTA = 32 batch rows, 8 warps (wm 0..1 x 16 rows, wn 0..3 x 7 n8-tiles).
// gates[32,224] = A[32,64] @ B[224,64]^T, passes AhiBhi + AloBhi + AhiBlo, f32 acc.
// A = [h | 1 | x_t | 0] bf16 hi/lo (SW128), double-buffered; B rows n=cell*4+gate,
// B_hi fragments register-resident, fused per-tile epilogue, 1 barrier/step.

#define T_LEN 256
#define HDIM  50
#define MB    32
#define NTHR  256
#define NTW   7
#define NROWS 224

// smem layout (bytes)
#define SM_XS   0                        // x_s[256][32] f32 = 32768
#define SM_A    32768                    // 2 planes x (hi 4096 + lo 4096) = 16384
#define SM_AHI(p) (SM_A + (p) * 8192)
#define SM_ALO(p) (SM_A + (p) * 8192 + 4096)
#define SM_BH   (SM_A + 16384)           // B_hi 224*128 = 28672
#define SM_BL   (SM_BH + 28672)
#define SM_RED  (SM_BL + 28672)          // red[32][8] f32 = 1024
#define SM_TOT  (SM_RED + 1024)          // 107520

typedef unsigned long long u64;

__device__ __forceinline__ uint32_t smem_u32(const void* p) {
    uint32_t a;
    asm("{ .reg .u64 t; cvta.to.shared.u64 t, %1; cvt.u32.u64 %0, t; }"
        : "=r"(a) : "l"(p));
    return a;
}
__device__ __forceinline__ uint32_t sw128(uint32_t b) {
    return b ^ ((b >> 3) & 0x70);
}
__device__ __forceinline__ float tanh_hw(float x) {
    float y; asm("tanh.approx.f32 %0, %1;" : "=f"(y) : "f"(x)); return y;
}
__device__ __forceinline__ float sigmoid_hw(float x) {
    return fmaf(0.5f, tanh_hw(0.5f * x), 0.5f);
}
__device__ __forceinline__ u64 pack2f(float a, float b) {
    u64 r; asm("mov.b64 %0, {%1, %2};" : "=l"(r) : "f"(a), "f"(b)); return r;
}
__device__ __forceinline__ float lo_of(u64 v) { return __uint_as_float((unsigned)v); }
__device__ __forceinline__ float hi_of(u64 v) { return __uint_as_float((unsigned)(v >> 32)); }

#define LDSM4(r0, r1, r2, r3, a) \
    asm volatile("ldmatrix.sync.aligned.m8n8.x4.shared.b16 {%0,%1,%2,%3}, [%4];" \
                 : "=r"(r0), "=r"(r1), "=r"(r2), "=r"(r3) : "r"(a))

__device__ __forceinline__ void mma_bf16(float* d, const uint32_t* a,
                                         const uint32_t* b) {
    asm volatile(
        "mma.sync.aligned.m16n8k16.row.col.f32.bf16.bf16.f32 "
        "{%0,%1,%2,%3}, {%4,%5,%6,%7}, {%8,%9}, {%0,%1,%2,%3};"
        : "+f"(d[0]), "+f"(d[1]), "+f"(d[2]), "+f"(d[3])
        : "r"(a[0]), "r"(a[1]), "r"(a[2]), "r"(a[3]), "r"(b[0]), "r"(b[1]));
}

__device__ __forceinline__ void store_bf16_split(char* smem, uint32_t hi_base,
                                                 uint32_t lo_base,
                                                 uint32_t byte_off, float v) {
    __nv_bfloat16 hi = __float2bfloat16(v);
    float lo = v - __bfloat162float(hi);
    uint32_t so = sw128(byte_off);
    *reinterpret_cast<__nv_bfloat16*>(smem + hi_base + so) = hi;
    *reinterpret_cast<__nv_bfloat16*>(smem + lo_base + so) = __float2bfloat16(lo);
}

__global__ __launch_bounds__(NTHR, 2) void lstm_mma_kernel(
    const float* __restrict__ x,      // [B, T, 1]
    const float* __restrict__ W_ih,   // [200, 1]
    const float* __restrict__ W_hh,   // [200, 50]
    const float* __restrict__ b_ih,   // [200]
    const float* __restrict__ b_hh,   // [200]
    const float* __restrict__ W_lin,  // [1, 50]
    const float* __restrict__ b_lin,  // [1]
    float* __restrict__ out)          // [B]
{
    extern __shared__ __align__(1024) char smem[];
    const uint32_t sb = smem_u32(smem);
    const int tid  = threadIdx.x;
    const int wid  = tid >> 5, lane = tid & 31;
    const int wm   = wid & 1, wn = wid >> 1;       // 2 x 4 warp grid
    const int m0   = wm * 16;
    const int nt0  = wn * NTW;
    const int b0   = blockIdx.x * MB;

    const int t3   = lane & 3;
    const int half = lane & 1;
    const int myrow = m0 + (lane >> 2) + 8 * half;  // 0..31

    float* x_s = reinterpret_cast<float*>(smem + SM_XS);

    // ---- load x tile (coalesced along t): x_s[t*32 + r]
    for (int i = tid; i < MB * T_LEN; i += NTHR) {
        int r = i >> 8, t = i & (T_LEN - 1);
        x_s[t * MB + r] = x[(size_t)(b0 + r) * T_LEN + t];
    }
    // ---- zero both A planes (hi+lo)
    for (int i = tid; i < 16384 / 4; i += NTHR)
        reinterpret_cast<uint32_t*>(smem + SM_A)[i] = 0u;
    // ---- build static B tiles (hi/lo), rows n = cell*4 + gate, K-major SW128
    for (int idx = tid; idx < NROWS * 64; idx += NTHR) {
        int n = idx >> 6, k = idx & 63;
        float v = 0.0f;
        if (n < 200) {
            int cell = n >> 2, gate = n & 3;
            int wr = gate * HDIM + cell;            // gate order i,f,g,o
            if (k < HDIM)           v = W_hh[wr * HDIM + k];
            else if (k == HDIM)     v = b_ih[wr] + b_hh[wr];
            else if (k == HDIM + 1) v = W_ih[wr];
        }
        store_bf16_split(smem, SM_BH, SM_BL, (uint32_t)(n * 128 + k * 2), v);
    }
    __syncthreads();
    // ---- ones column (k=50, both planes) + x column (k=51) for t=0 (plane 0)
    if (tid < MB) {
        uint32_t so = sw128((uint32_t)(tid * 128 + HDIM * 2));
        *reinterpret_cast<__nv_bfloat16*>(smem + SM_AHI(0) + so) = __float2bfloat16(1.0f);
        *reinterpret_cast<__nv_bfloat16*>(smem + SM_AHI(1) + so) = __float2bfloat16(1.0f);
        store_bf16_split(smem, SM_AHI(0), SM_ALO(0),
                         (uint32_t)(tid * 128 + (HDIM + 1) * 2), x_s[tid]);
    }
    __syncthreads();   // B tiles complete before resident LDSM

    // ---- fragment addresses
    const uint32_t a_m    = (uint32_t)(m0 + (lane & 7) + 8 * ((lane >> 3) & 1));
    const uint32_t a_koff = (uint32_t)(8 * (lane >> 4));
    const uint32_t b_nrow = (uint32_t)(lane & 7);
    const uint32_t b_koff = (uint32_t)(8 * (lane >> 3));

    // ---- B_hi fragments RESIDENT (7 tiles x 8 regs)
    uint32_t bhr[NTW][8];
    #pragma unroll
    for (int nt = 0; nt < NTW; nt++) {
        uint32_t n = (uint32_t)((nt0 + nt) * 8) + b_nrow;
        uint32_t so0 = sw128(n * 128 + b_koff * 2);
        uint32_t so1 = sw128(n * 128 + (32 + b_koff) * 2);
        LDSM4(bhr[nt][0], bhr[nt][1], bhr[nt][2], bhr[nt][3], sb + SM_BH + so0);
        LDSM4(bhr[nt][4], bhr[nt][5], bhr[nt][6], bhr[nt][7], sb + SM_BH + so1);
    }

    float cst[NTW];
    #pragma unroll
    for (int nt = 0; nt < NTW; nt++) cst[nt] = 0.0f;
    float partial = 0.0f;

    #pragma unroll 1
    for (int t = 0; t < T_LEN; t++) {
        __syncthreads();   // plane p fully written (h from t-1, x col)
        const int p = t & 1;
        const uint32_t ahi = SM_AHI(p), alo = SM_ALO(p);
        const uint32_t nhi = SM_AHI(p ^ 1), nlo = SM_ALO(p ^ 1);

        // ---- A fragments: 4 k-tiles x (hi, lo)
        uint32_t ah[16], al[16];
        #pragma unroll
        for (int kt = 0; kt < 4; kt++) {
            uint32_t so = sw128(a_m * 128 + ((uint32_t)(kt * 16) + a_koff) * 2);
            LDSM4(ah[4*kt], ah[4*kt+1], ah[4*kt+2], ah[4*kt+3], sb + ahi + so);
            LDSM4(al[4*kt], al[4*kt+1], al[4*kt+2], al[4*kt+3], sb + alo + so);
        }

        // ---- per n-tile: B_lo load + 12 MMA + fused epilogue
        #pragma unroll
        for (int nt = 0; nt < NTW; nt++) {
            uint32_t n = (uint32_t)((nt0 + nt) * 8) + b_nrow;
            uint32_t bl[8];
            {
                uint32_t so0 = sw128(n * 128 + b_koff * 2);
                uint32_t so1 = sw128(n * 128 + (32 + b_koff) * 2);
                LDSM4(bl[0], bl[1], bl[2], bl[3], sb + SM_BL + so0);
                LDSM4(bl[4], bl[5], bl[6], bl[7], sb + SM_BL + so1);
            }
            float d[4] = {0.0f, 0.0f, 0.0f, 0.0f};
            #pragma unroll
            for (int kt = 0; kt < 4; kt++)
                mma_bf16(d, ah + 4 * kt, bhr[nt] + 2 * kt);
            #pragma unroll
            for (int kt = 0; kt < 4; kt++)
                mma_bf16(d, al + 4 * kt, bhr[nt] + 2 * kt);
            #pragma unroll
            for (int kt = 0; kt < 4; kt++)
                mma_bf16(d, ah + 4 * kt, bl + 2 * kt);

            // ---- epilogue for this tile
            u64 send = half ? pack2f(d[0], d[1]) : pack2f(d[2], d[3]);
            u64 recv = __shfl_xor_sync(0xffffffffu, send, 1);
            float gi, gf, gg, go;
            if (half == 0) {
                gi = d[0]; gf = d[1]; gg = lo_of(recv); go = hi_of(recv);
            } else {
                gg = d[2]; go = d[3]; gi = lo_of(recv); gf = hi_of(recv);
            }
            float i_ = sigmoid_hw(gi);
            float f_ = sigmoid_hw(gf);
            float g_ = tanh_hw(gg);
            float o_ = sigmoid_hw(go);
            cst[nt] = fmaf(f_, cst[nt], i_ * g_);
            float hn = o_ * tanh_hw(cst[nt]);
            int cell = (nt0 + nt) * 2 + (t3 >> 1);
            if (cell < HDIM) {
                store_bf16_split(smem, nhi, nlo,
                                 (uint32_t)(myrow * 128 + cell * 2), hn);
                if (t == T_LEN - 1)
                    partial = fmaf(__ldg(&W_lin[cell]), hn, partial);
            }
        }
        // ---- x column for next step into next plane
        if (tid < MB && t + 1 < T_LEN) {
            store_bf16_split(smem, nhi, nlo,
                             (uint32_t)(tid * 128 + (HDIM + 1) * 2),
                             x_s[(t + 1) * MB + tid]);
        }
    }

    // ---- final linear: reduce 8 partials per row
    float* red = reinterpret_cast<float*>(smem + SM_RED);
    int slot = wn * 2 + (t3 >> 1);
    red[myrow * 8 + slot] = partial;
    __syncthreads();
    if (tid < MB) {
        float s = b_lin[0];
        #pragma unroll
        for (int i = 0; i < 8; i++) s += red[tid * 8 + i];
        out[b0 + tid] = s;
    }
}

extern "C" void kernel_launch(void* const* d_in, const int* in_sizes, int n_in,
                              void* d_out, int out_size) {
    const float* x     = (const float*)d_in[0];
    const float* W_ih  = (const float*)d_in[1];
    const float* W_hh  = (const float*)d_in[2];
    const float* b_ih  = (const float*)d_in[3];
    const float* b_hh  = (const float*)d_in[4];
    const float* W_lin = (const float*)d_in[5];
    const float* b_lin = (const float*)d_in[6];
    float* out = (float*)d_out;

    int Btot = in_sizes[0] / T_LEN;   // 8192

    static int smem_set = 0;
    if (!smem_set) {
        cudaFuncSetAttribute(lstm_mma_kernel,
                             cudaFuncAttributeMaxDynamicSharedMemorySize, SM_TOT);
        smem_set = 1;
    }
    lstm_mma_kernel<<<Btot / MB, NTHR, SM_TOT>>>(
        x, W_ih, W_hh, b_ih, b_hh, W_lin, b_lin, out);
}

// round 16
// speedup vs baseline: 1.0659x; 1.0659x over previous
#include <cuda_runtime.h>
#include <cuda_bf16.h>
#include <cstdint>

// LSTM_53815940218945 via mma.sync bf16x3 (Ootomo split), round 16:
// R14 config (MB=64, 512 thr, 16 warps, B_hi register-resident, fused epilogue,
// double-buffered A) + GROUP DESYNC: the batch dim is block-diagonal, so warp
// group wm (4 warps, 16 batch rows) is an independent LSTM. Per-step sync is a
// named barrier over 128 threads (bar.sync wm+1), NOT __syncthreads -> the 4
// groups drift and overlap each other's latency tails.
// gates[16,224] per group = A[16,64] @ B[224,64]^T, passes AhiBhi+AloBhi+AhiBlo.
// A = [h | 1 | x_t | 0] bf16 hi/lo (SW128); B rows n = cell*4+gate (static).

#define T_LEN 256
#define HDIM  50
#define MB    64
#define NTHR  512
#define NTW   7
#define NROWS 224

// smem layout (bytes)
#define SM_XS   0                        // x_s[256][64] f32 = 65536
#define SM_A    65536                    // 2 planes x (hi 8192 + lo 8192)
#define SM_AHI(p) (SM_A + (p) * 16384)
#define SM_ALO(p) (SM_A + (p) * 16384 + 8192)
#define SM_BH   (SM_A + 32768)           // B_hi 224*128 = 28672
#define SM_BL   (SM_BH + 28672)
#define SM_RED  (SM_BL + 28672)          // red[64][8] f32 = 2048
#define SM_TOT  (SM_RED + 2048)          // 157696

typedef unsigned long long u64;

__device__ __forceinline__ uint32_t smem_u32(const void* p) {
    uint32_t a;
    asm("{ .reg .u64 t; cvta.to.shared.u64 t, %1; cvt.u32.u64 %0, t; }"
        : "=r"(a) : "l"(p));
    return a;
}
__device__ __forceinline__ uint32_t sw128(uint32_t b) {
    return b ^ ((b >> 3) & 0x70);
}
__device__ __forceinline__ float tanh_hw(float x) {
    float y; asm("tanh.approx.f32 %0, %1;" : "=f"(y) : "f"(x)); return y;
}
__device__ __forceinline__ float sigmoid_hw(float x) {
    return fmaf(0.5f, tanh_hw(0.5f * x), 0.5f);
}
__device__ __forceinline__ u64 pack2f(float a, float b) {
    u64 r; asm("mov.b64 %0, {%1, %2};" : "=l"(r) : "f"(a), "f"(b)); return r;
}
__device__ __forceinline__ float lo_of(u64 v) { return __uint_as_float((unsigned)v); }
__device__ __forceinline__ float hi_of(u64 v) { return __uint_as_float((unsigned)(v >> 32)); }

// group barrier: 128 threads of warp-group g (warps {g, g+4, g+8, g+12})
#define GBAR(g) asm volatile("bar.sync %0, %1;" :: "r"((g) + 1), "r"(128) : "memory")

#define LDSM4(r0, r1, r2, r3, a) \
    asm volatile("ldmatrix.sync.aligned.m8n8.x4.shared.b16 {%0,%1,%2,%3}, [%4];" \
                 : "=r"(r0), "=r"(r1), "=r"(r2), "=r"(r3) : "r"(a))

__device__ __forceinline__ void mma_bf16(float* d, const uint32_t* a,
                                         const uint32_t* b) {
    asm volatile(
        "mma.sync.aligned.m16n8k16.row.col.f32.bf16.bf16.f32 "
        "{%0,%1,%2,%3}, {%4,%5,%6,%7}, {%8,%9}, {%0,%1,%2,%3};"
        : "+f"(d[0]), "+f"(d[1]), "+f"(d[2]), "+f"(d[3])
        : "r"(a[0]), "r"(a[1]), "r"(a[2]), "r"(a[3]), "r"(b[0]), "r"(b[1]));
}

__device__ __forceinline__ void store_bf16_split(char* smem, uint32_t hi_base,
                                                 uint32_t lo_base,
                                                 uint32_t byte_off, float v) {
    __nv_bfloat16 hi = __float2bfloat16(v);
    float lo = v - __bfloat162float(hi);
    uint32_t so = sw128(byte_off);
    *reinterpret_cast<__nv_bfloat16*>(smem + hi_base + so) = hi;
    *reinterpret_cast<__nv_bfloat16*>(smem + lo_base + so) = __float2bfloat16(lo);
}

__global__ __launch_bounds__(NTHR, 1) void lstm_mma_kernel(
    const float* __restrict__ x,      // [B, T, 1]
    const float* __restrict__ W_ih,   // [200, 1]
    const float* __restrict__ W_hh,   // [200, 50]
    const float* __restrict__ b_ih,   // [200]
    const float* __restrict__ b_hh,   // [200]
    const float* __restrict__ W_lin,  // [1, 50]
    const float* __restrict__ b_lin,  // [1]
    float* __restrict__ out)          // [B]
{
    extern __shared__ __align__(1024) char smem[];
    const uint32_t sb = smem_u32(smem);
    const int tid  = threadIdx.x;
    const int wid  = tid >> 5, lane = tid & 31;
    const int wm   = wid & 3, wn = wid >> 2;
    const int m0   = wm * 16;
    const int nt0  = wn * NTW;
    const int b0   = blockIdx.x * MB;

    const int t3   = lane & 3;
    const int half = lane & 1;
    const int myrow = m0 + (lane >> 2) + 8 * half;     // row this thread updates
    // x-column owner: one thread per row per group (warp wn==0, cell-parity 0)
    const bool xowner = (wn == 0) && ((t3 >> 1) == 0);

    float* x_s = reinterpret_cast<float*>(smem + SM_XS);

    // ---- load x tile (coalesced along t)
    for (int i = tid; i < MB * T_LEN; i += NTHR) {
        int r = i >> 8, t = i & (T_LEN - 1);
        x_s[t * MB + r] = x[(size_t)(b0 + r) * T_LEN + t];
    }
    // ---- zero both A planes (hi+lo)
    for (int i = tid; i < 32768 / 4; i += NTHR)
        reinterpret_cast<uint32_t*>(smem + SM_A)[i] = 0u;
    // ---- build static B tiles (hi/lo), rows n = cell*4 + gate, K-major SW128
    for (int idx = tid; idx < NROWS * 64; idx += NTHR) {
        int n = idx >> 6, k = idx & 63;
        float v = 0.0f;
        if (n < 200) {
            int cell = n >> 2, gate = n & 3;
            int wr = gate * HDIM + cell;            // gate order i,f,g,o
            if (k < HDIM)           v = W_hh[wr * HDIM + k];
            else if (k == HDIM)     v = b_ih[wr] + b_hh[wr];
            else if (k == HDIM + 1) v = W_ih[wr];
        }
        store_bf16_split(smem, SM_BH, SM_BL, (uint32_t)(n * 128 + k * 2), v);
    }
    __syncthreads();
    // ---- ones column (k=50, both planes) + x column (k=51) for t=0 (plane 0)
    if (tid < MB) {
        uint32_t so = sw128((uint32_t)(tid * 128 + HDIM * 2));
        *reinterpret_cast<__nv_bfloat16*>(smem + SM_AHI(0) + so) = __float2bfloat16(1.0f);
        *reinterpret_cast<__nv_bfloat16*>(smem + SM_AHI(1) + so) = __float2bfloat16(1.0f);
        store_bf16_split(smem, SM_AHI(0), SM_ALO(0),
                         (uint32_t)(tid * 128 + (HDIM + 1) * 2), x_s[tid]);
    }
    __syncthreads();   // B tiles + plane-0 init complete

    // ---- fragment addresses
    const uint32_t a_m    = (uint32_t)(m0 + (lane & 7) + 8 * ((lane >> 3) & 1));
    const uint32_t a_koff = (uint32_t)(8 * (lane >> 4));
    const uint32_t b_nrow = (uint32_t)(lane & 7);
    const uint32_t b_koff = (uint32_t)(8 * (lane >> 3));

    // ---- B_hi fragments RESIDENT (7 tiles x 8 regs)
    uint32_t bhr[NTW][8];
    #pragma unroll
    for (int nt = 0; nt < NTW; nt++) {
        uint32_t n = (uint32_t)((nt0 + nt) * 8) + b_nrow;
        uint32_t so0 = sw128(n * 128 + b_koff * 2);
        uint32_t so1 = sw128(n * 128 + (32 + b_koff) * 2);
        LDSM4(bhr[nt][0], bhr[nt][1], bhr[nt][2], bhr[nt][3], sb + SM_BH + so0);
        LDSM4(bhr[nt][4], bhr[nt][5], bhr[nt][6], bhr[nt][7], sb + SM_BH + so1);
    }

    float cst[NTW];
    #pragma unroll
    for (int nt = 0; nt < NTW; nt++) cst[nt] = 0.0f;
    float partial = 0.0f;

    #pragma unroll 1
    for (int t = 0; t < T_LEN; t++) {
        GBAR(wm);          // group-local: my 16 rows fully written for step t
        const int p = t & 1;
        const uint32_t ahi = SM_AHI(p), alo = SM_ALO(p);
        const uint32_t nhi = SM_AHI(p ^ 1), nlo = SM_ALO(p ^ 1);

        // ---- A fragments: 4 k-tiles x (hi, lo)
        uint32_t ah[16], al[16];
        #pragma unroll
        for (int kt = 0; kt < 4; kt++) {
            uint32_t so = sw128(a_m * 128 + ((uint32_t)(kt * 16) + a_koff) * 2);
            LDSM4(ah[4*kt], ah[4*kt+1], ah[4*kt+2], ah[4*kt+3], sb + ahi + so);
            LDSM4(al[4*kt], al[4*kt+1], al[4*kt+2], al[4*kt+3], sb + alo + so);
        }

        // ---- per n-tile: B_lo load + 12 MMA + fused epilogue
        #pragma unroll
        for (int nt = 0; nt < NTW; nt++) {
            uint32_t n = (uint32_t)((nt0 + nt) * 8) + b_nrow;
            uint32_t bl[8];
            {
                uint32_t so0 = sw128(n * 128 + b_koff * 2);
                uint32_t so1 = sw128(n * 128 + (32 + b_koff) * 2);
                LDSM4(bl[0], bl[1], bl[2], bl[3], sb + SM_BL + so0);
                LDSM4(bl[4], bl[5], bl[6], bl[7], sb + SM_BL + so1);
            }
            float d[4] = {0.0f, 0.0f, 0.0f, 0.0f};
            #pragma unroll
            for (int kt = 0; kt < 4; kt++)
                mma_bf16(d, ah + 4 * kt, bhr[nt] + 2 * kt);
            #pragma unroll
            for (int kt = 0; kt < 4; kt++)
                mma_bf16(d, al + 4 * kt, bhr[nt] + 2 * kt);
            #pragma unroll
            for (int kt = 0; kt < 4; kt++)
                mma_bf16(d, ah + 4 * kt, bl + 2 * kt);

            // ---- epilogue for this tile
            u64 send = half ? pack2f(d[0], d[1]) : pack2f(d[2], d[3]);
            u64 recv = __shfl_xor_sync(0xffffffffu, send, 1);
            float gi, gf, gg, go;
            if (half == 0) {
                gi = d[0]; gf = d[1]; gg = lo_of(recv); go = hi_of(recv);
            } else {
                gg = d[2]; go = d[3]; gi = lo_of(recv); gf = hi_of(recv);
            }
            float i_ = sigmoid_hw(gi);
            float f_ = sigmoid_hw(gf);
            float g_ = tanh_hw(gg);
            float o_ = sigmoid_hw(go);
            cst[nt] = fmaf(f_, cst[nt], i_ * g_);
            float hn = o_ * tanh_hw(cst[nt]);
            int cell = (nt0 + nt) * 2 + (t3 >> 1);
            if (cell < HDIM) {
                store_bf16_split(smem, nhi, nlo,
                                 (uint32_t)(myrow * 128 + cell * 2), hn);
                if (t == T_LEN - 1)
                    partial = fmaf(__ldg(&W_lin[cell]), hn, partial);
            }
        }
        // ---- x column for next step (group-local owner per row)
        if (xowner && t + 1 < T_LEN) {
            store_bf16_split(smem, nhi, nlo,
                             (uint32_t)(myrow * 128 + (HDIM + 1) * 2),
                             x_s[(t + 1) * MB + myrow]);
        }
    }

    // ---- final linear: reduce 8 partials per row
    float* red = reinterpret_cast<float*>(smem + SM_RED);
    int slot = wn * 2 + (t3 >> 1);
    red[myrow * 8 + slot] = partial;
    __syncthreads();
    if (tid < MB) {
        float s = b_lin[0];
        #pragma unroll
        for (int i = 0; i < 8; i++) s += red[tid * 8 + i];
        out[b0 + tid] = s;
    }
}

extern "C" void kernel_launch(void* const* d_in, const int* in_sizes, int n_in,
                              void* d_out, int out_size) {
    const float* x     = (const float*)d_in[0];
    const float* W_ih  = (const float*)d_in[1];
    const float* W_hh  = (const float*)d_in[2];
    const float* b_ih  = (const float*)d_in[3];
    const float* b_hh  = (const float*)d_in[4];
    const float* W_lin = (const float*)d_in[5];
    const float* b_lin = (const float*)d_in[6];
    float* out = (float*)d_out;

    int Btot = in_sizes[0] / T_LEN;   // 8192

    static int smem_set = 0;
    if (!smem_set) {
        cudaFuncSetAttribute(lstm_mma_kernel,
                             cudaFuncAttributeMaxDynamicSharedMemorySize, SM_TOT);
        smem_set = 1;
    }
    lstm_mma_kernel<<<Btot / MB, NTHR, SM_TOT>>>(
        x, W_ih, W_hh, b_ih, b_hh, W_lin, b_lin, out);
}

// round 17
// speedup vs baseline: 1.1696x; 1.0973x over previous
#include <cuda_runtime.h>
#include <cuda_bf16.h>
#include <cstdint>

// LSTM_53815940218945 via mma.sync bf16x3 (Ootomo split), round 17:
// R16 (named-barrier group desync, B_hi resident, fused epilogue) +
//  - pad-tile trim: 25 real n8-tiles (cells 0..49), warps get 7/6/6/6
//  - K-tail trim: AloBhi pass skips k-tile 3 (error ~1e-6; bias-lo kept
//    via AhiBlo kt3) -> 11 MMA/tile, A-lo frags only 3 k-tiles.
// gates[16,200] per group = A[16,64] @ B[200,64]^T.

#define T_LEN 256
#define HDIM  50
#define MB    64
#define NTHR  512
#define NTWMAX 7
#define NROWS 224

// smem layout (bytes)
#define SM_XS   0                        // x_s[256][64] f32 = 65536
#define SM_A    65536                    // 2 planes x (hi 8192 + lo 8192)
#define SM_AHI(p) (SM_A + (p) * 16384)
#define SM_ALO(p) (SM_A + (p) * 16384 + 8192)
#define SM_BH   (SM_A + 32768)           // B_hi 224*128 = 28672
#define SM_BL   (SM_BH + 28672)
#define SM_RED  (SM_BL + 28672)          // red[64][8] f32 = 2048
#define SM_TOT  (SM_RED + 2048)          // 157696

typedef unsigned long long u64;

__device__ __forceinline__ uint32_t smem_u32(const void* p) {
    uint32_t a;
    asm("{ .reg .u64 t; cvta.to.shared.u64 t, %1; cvt.u32.u64 %0, t; }"
        : "=r"(a) : "l"(p));
    return a;
}
__device__ __forceinline__ uint32_t sw128(uint32_t b) {
    return b ^ ((b >> 3) & 0x70);
}
__device__ __forceinline__ float tanh_hw(float x) {
    float y; asm("tanh.approx.f32 %0, %1;" : "=f"(y) : "f"(x)); return y;
}
__device__ __forceinline__ float sigmoid_hw(float x) {
    return fmaf(0.5f, tanh_hw(0.5f * x), 0.5f);
}
__device__ __forceinline__ u64 pack2f(float a, float b) {
    u64 r; asm("mov.b64 %0, {%1, %2};" : "=l"(r) : "f"(a), "f"(b)); return r;
}
__device__ __forceinline__ float lo_of(u64 v) { return __uint_as_float((unsigned)v); }
__device__ __forceinline__ float hi_of(u64 v) { return __uint_as_float((unsigned)(v >> 32)); }

// group barrier: 128 threads of warp-group g (warps {g, g+4, g+8, g+12})
#define GBAR(g) asm volatile("bar.sync %0, %1;" :: "r"((g) + 1), "r"(128) : "memory")

#define LDSM4(r0, r1, r2, r3, a) \
    asm volatile("ldmatrix.sync.aligned.m8n8.x4.shared.b16 {%0,%1,%2,%3}, [%4];" \
                 : "=r"(r0), "=r"(r1), "=r"(r2), "=r"(r3) : "r"(a))

__device__ __forceinline__ void mma_bf16(float* d, const uint32_t* a,
                                         const uint32_t* b) {
    asm volatile(
        "mma.sync.aligned.m16n8k16.row.col.f32.bf16.bf16.f32 "
        "{%0,%1,%2,%3}, {%4,%5,%6,%7}, {%8,%9}, {%0,%1,%2,%3};"
        : "+f"(d[0]), "+f"(d[1]), "+f"(d[2]), "+f"(d[3])
        : "r"(a[0]), "r"(a[1]), "r"(a[2]), "r"(a[3]), "r"(b[0]), "r"(b[1]));
}

__device__ __forceinline__ void store_bf16_split(char* smem, uint32_t hi_base,
                                                 uint32_t lo_base,
                                                 uint32_t byte_off, float v) {
    __nv_bfloat16 hi = __float2bfloat16(v);
    float lo = v - __bfloat162float(hi);
    uint32_t so = sw128(byte_off);
    *reinterpret_cast<__nv_bfloat16*>(smem + hi_base + so) = hi;
    *reinterpret_cast<__nv_bfloat16*>(smem + lo_base + so) = __float2bfloat16(lo);
}

__global__ __launch_bounds__(NTHR, 1) void lstm_mma_kernel(
    const float* __restrict__ x,      // [B, T, 1]
    const float* __restrict__ W_ih,   // [200, 1]
    const float* __restrict__ W_hh,   // [200, 50]
    const float* __restrict__ b_ih,   // [200]
    const float* __restrict__ b_hh,   // [200]
    const float* __restrict__ W_lin,  // [1, 50]
    const float* __restrict__ b_lin,  // [1]
    float* __restrict__ out)          // [B]
{
    extern __shared__ __align__(1024) char smem[];
    const uint32_t sb = smem_u32(smem);
    const int tid  = threadIdx.x;
    const int wid  = tid >> 5, lane = tid & 31;
    const int wm   = wid & 3, wn = wid >> 2;
    const int m0   = wm * 16;
    const int b0   = blockIdx.x * MB;

    // tile distribution over wn: 7,6,6,6 real tiles (25 total = cells 0..49)
    const int ncnt = (wn == 0) ? 7 : 6;
    const int nt0  = (wn == 0) ? 0 : 7 + 6 * (wn - 1);   // 0,7,13,19

    const int t3   = lane & 3;
    const int half = lane & 1;
    const int myrow = m0 + (lane >> 2) + 8 * half;
    const bool xowner = (wn == 0) && ((t3 >> 1) == 0);

    float* x_s = reinterpret_cast<float*>(smem + SM_XS);

    // ---- load x tile (coalesced along t)
    for (int i = tid; i < MB * T_LEN; i += NTHR) {
        int r = i >> 8, t = i & (T_LEN - 1);
        x_s[t * MB + r] = x[(size_t)(b0 + r) * T_LEN + t];
    }
    // ---- zero both A planes (hi+lo)
    for (int i = tid; i < 32768 / 4; i += NTHR)
        reinterpret_cast<uint32_t*>(smem + SM_A)[i] = 0u;
    // ---- build static B tiles (hi/lo), rows n = cell*4 + gate, K-major SW128
    for (int idx = tid; idx < NROWS * 64; idx += NTHR) {
        int n = idx >> 6, k = idx & 63;
        float v = 0.0f;
        if (n < 200) {
            int cell = n >> 2, gate = n & 3;
            int wr = gate * HDIM + cell;            // gate order i,f,g,o
            if (k < HDIM)           v = W_hh[wr * HDIM + k];
            else if (k == HDIM)     v = b_ih[wr] + b_hh[wr];
            else if (k == HDIM + 1) v = W_ih[wr];
        }
        store_bf16_split(smem, SM_BH, SM_BL, (uint32_t)(n * 128 + k * 2), v);
    }
    __syncthreads();
    // ---- ones column (k=50, both planes) + x column (k=51) for t=0 (plane 0)
    if (tid < MB) {
        uint32_t so = sw128((uint32_t)(tid * 128 + HDIM * 2));
        *reinterpret_cast<__nv_bfloat16*>(smem + SM_AHI(0) + so) = __float2bfloat16(1.0f);
        *reinterpret_cast<__nv_bfloat16*>(smem + SM_AHI(1) + so) = __float2bfloat16(1.0f);
        store_bf16_split(smem, SM_AHI(0), SM_ALO(0),
                         (uint32_t)(tid * 128 + (HDIM + 1) * 2), x_s[tid]);
    }
    __syncthreads();   // B tiles + plane-0 init complete

    // ---- fragment addresses
    const uint32_t a_m    = (uint32_t)(m0 + (lane & 7) + 8 * ((lane >> 3) & 1));
    const uint32_t a_koff = (uint32_t)(8 * (lane >> 4));
    const uint32_t b_nrow = (uint32_t)(lane & 7);
    const uint32_t b_koff = (uint32_t)(8 * (lane >> 3));

    // ---- B_hi fragments RESIDENT (up to 7 tiles x 8 regs), guarded
    uint32_t bhr[NTWMAX][8];
    #pragma unroll
    for (int nt = 0; nt < NTWMAX; nt++) {
        if (nt < ncnt) {
            uint32_t n = (uint32_t)((nt0 + nt) * 8) + b_nrow;
            uint32_t so0 = sw128(n * 128 + b_koff * 2);
            uint32_t so1 = sw128(n * 128 + (32 + b_koff) * 2);
            LDSM4(bhr[nt][0], bhr[nt][1], bhr[nt][2], bhr[nt][3], sb + SM_BH + so0);
            LDSM4(bhr[nt][4], bhr[nt][5], bhr[nt][6], bhr[nt][7], sb + SM_BH + so1);
        }
    }

    float cst[NTWMAX];
    #pragma unroll
    for (int nt = 0; nt < NTWMAX; nt++) cst[nt] = 0.0f;
    float partial = 0.0f;

    #pragma unroll 1
    for (int t = 0; t < T_LEN; t++) {
        GBAR(wm);          // group-local: my 16 rows fully written for step t
        const int p = t & 1;
        const uint32_t ahi = SM_AHI(p), alo = SM_ALO(p);
        const uint32_t nhi = SM_AHI(p ^ 1), nlo = SM_ALO(p ^ 1);

        // ---- A fragments: hi 4 k-tiles, lo 3 k-tiles (kt3 lo-pass dropped)
        uint32_t ah[16], al[12];
        #pragma unroll
        for (int kt = 0; kt < 4; kt++) {
            uint32_t so = sw128(a_m * 128 + ((uint32_t)(kt * 16) + a_koff) * 2);
            LDSM4(ah[4*kt], ah[4*kt+1], ah[4*kt+2], ah[4*kt+3], sb + ahi + so);
            if (kt < 3)
                LDSM4(al[4*kt], al[4*kt+1], al[4*kt+2], al[4*kt+3], sb + alo + so);
        }

        // ---- per n-tile: B_lo load + 11 MMA + fused epilogue
        #pragma unroll
        for (int nt = 0; nt < NTWMAX; nt++) {
            if (nt >= ncnt) break;
            uint32_t n = (uint32_t)((nt0 + nt) * 8) + b_nrow;
            uint32_t bl[8];
            {
                uint32_t so0 = sw128(n * 128 + b_koff * 2);
                uint32_t so1 = sw128(n * 128 + (32 + b_koff) * 2);
                LDSM4(bl[0], bl[1], bl[2], bl[3], sb + SM_BL + so0);
                LDSM4(bl[4], bl[5], bl[6], bl[7], sb + SM_BL + so1);
            }
            float d[4] = {0.0f, 0.0f, 0.0f, 0.0f};
            #pragma unroll
            for (int kt = 0; kt < 4; kt++)
                mma_bf16(d, ah + 4 * kt, bhr[nt] + 2 * kt);   // AhiBhi (4)
            #pragma unroll
            for (int kt = 0; kt < 3; kt++)
                mma_bf16(d, al + 4 * kt, bhr[nt] + 2 * kt);   // AloBhi (3)
            #pragma unroll
            for (int kt = 0; kt < 4; kt++)
                mma_bf16(d, ah + 4 * kt, bl + 2 * kt);        // AhiBlo (4)

            // ---- epilogue for this tile
            u64 send = half ? pack2f(d[0], d[1]) : pack2f(d[2], d[3]);
            u64 recv = __shfl_xor_sync(0xffffffffu, send, 1);
            float gi, gf, gg, go;
            if (half == 0) {
                gi = d[0]; gf = d[1]; gg = lo_of(recv); go = hi_of(recv);
            } else {
                gg = d[2]; go = d[3]; gi = lo_of(recv); gf = hi_of(recv);
            }
            float i_ = sigmoid_hw(gi);
            float f_ = sigmoid_hw(gf);
            float g_ = tanh_hw(gg);
            float o_ = sigmoid_hw(go);
            cst[nt] = fmaf(f_, cst[nt], i_ * g_);
            float hn = o_ * tanh_hw(cst[nt]);
            int cell = (nt0 + nt) * 2 + (t3 >> 1);   // always < 50 now
            store_bf16_split(smem, nhi, nlo,
                             (uint32_t)(myrow * 128 + cell * 2), hn);
            if (t == T_LEN - 1)
                partial = fmaf(__ldg(&W_lin[cell]), hn, partial);
        }
        // ---- x column for next step (group-local owner per row)
        if (xowner && t + 1 < T_LEN) {
            store_bf16_split(smem, nhi, nlo,
                             (uint32_t)(myrow * 128 + (HDIM + 1) * 2),
                             x_s[(t + 1) * MB + myrow]);
        }
    }

    // ---- final linear: reduce 8 partials per row
    float* red = reinterpret_cast<float*>(smem + SM_RED);
    int slot = wn * 2 + (t3 >> 1);
    red[myrow * 8 + slot] = partial;
    __syncthreads();
    if (tid < MB) {
        float s = b_lin[0];
        #pragma unroll
        for (int i = 0; i < 8; i++) s += red[tid * 8 + i];
        out[b0 + tid] = s;
    }
}

extern "C" void kernel_launch(void* const* d_in, const int* in_sizes, int n_in,
                              void* d_out, int out_size) {
    const float* x     = (const float*)d_in[0];
    const float* W_ih  = (const float*)d_in[1];
    const float* W_hh  = (const float*)d_in[2];
    const float* b_ih  = (const float*)d_in[3];
    const float* b_hh  = (const float*)d_in[4];
    const float* W_lin = (const float*)d_in[5];
    const float* b_lin = (const float*)d_in[6];
    float* out = (float*)d_out;

    int Btot = in_sizes[0] / T_LEN;   // 8192

    static int smem_set = 0;
    if (!smem_set) {
        cudaFuncSetAttribute(lstm_mma_kernel,
                             cudaFuncAttributeMaxDynamicSharedMemorySize, SM_TOT);
        smem_set = 1;
    }
    lstm_mma_kernel<<<Btot / MB, NTHR, SM_TOT>>>(
        x, W_ih, W_hh, b_ih, b_hh, W_lin, b_lin, out);
}